// round 13
// baseline (speedup 1.0000x reference)
#include <cuda_runtime.h>
#include <cuda_bf16.h>
#include <math.h>
#include <cstdint>

// Problem dims
#define B_SZ 512
#define T_IN 1125
#define E_SZ 5
#define C_SZ 40
#define L_SZ 216
#define G_SZ 40
#define H_SZ 10
#define KK   125

// ---- persistent scratch ----
__device__ __align__(16) float d_bg[G_SZ];
__device__ __align__(16) uint16_t d_Wbfhi[G_SZ*136];    // bf16 W[n][k], k padded to 136
__device__ __align__(16) uint16_t d_Wbflo[G_SZ*136];

__device__ __forceinline__ float tanh_a(float x) {
    float r; asm("tanh.approx.f32 %0, %1;" : "=f"(r) : "f"(x)); return r;
}
__device__ __forceinline__ uint32_t smem_u32(const void* p) {
    uint32_t a;
    asm("{ .reg .u64 t; cvta.to.shared.u64 t, %1; cvt.u32.u64 %0, t; }" : "=r"(a) : "l"(p));
    return a;
}
__device__ __forceinline__ void ldsm_x4(uint32_t* r, uint32_t addr) {
    asm volatile("ldmatrix.sync.aligned.m8n8.x4.shared.b16 {%0,%1,%2,%3}, [%4];"
        : "=r"(r[0]), "=r"(r[1]), "=r"(r[2]), "=r"(r[3]) : "r"(addr));
}
__device__ __forceinline__ void ldsm_x2(uint32_t* r, uint32_t addr) {
    asm volatile("ldmatrix.sync.aligned.m8n8.x2.shared.b16 {%0,%1}, [%2];"
        : "=r"(r[0]), "=r"(r[1]) : "r"(addr));
}
__device__ __forceinline__ void mma_bf16(float* d, const uint32_t* a, const uint32_t* b) {
    asm volatile("mma.sync.aligned.m16n8k16.row.col.f32.bf16.bf16.f32 "
        "{%0,%1,%2,%3}, {%4,%5,%6,%7}, {%8,%9}, {%0,%1,%2,%3};"
        : "+f"(d[0]), "+f"(d[1]), "+f"(d[2]), "+f"(d[3])
        : "r"(a[0]), "r"(a[1]), "r"(a[2]), "r"(a[3]), "r"(b[0]), "r"(b[1]));
}
__device__ __forceinline__ uint16_t bf16_rn(float v) {
    __nv_bfloat16 h = __float2bfloat16(v);
    return *reinterpret_cast<uint16_t*>(&h);
}

// ============================================================
// Kernel 0: weight fold -> bf16 hi/lo images [40][136] + bg[40].
// (R12 verbatim — proven)
// ============================================================
__global__ void __launch_bounds__(256) prep_kernel(
        const float* __restrict__ wt,     // [40][25]
        const float* __restrict__ tb,     // [40]
        const float* __restrict__ ws,     // [40][40][5]
        const float* __restrict__ gamma,
        const float* __restrict__ beta,
        const float* __restrict__ mean,
        const float* __restrict__ var,
        const float* __restrict__ wih,    // [40][40]
        const float* __restrict__ bih,
        const float* __restrict__ bhh)
{
    __shared__ __align__(16) float s_ws[C_SZ*C_SZ*E_SZ];   // 8000
    __shared__ __align__(16) float s_wt[C_SZ*25];
    __shared__ float s_wr[C_SZ], s_wsc[C_SZ], s_shift[C_SZ], s_tb[C_SZ];
    __shared__ float A_s[C_SZ*E_SZ];
    __shared__ float red[8];
    int t = threadIdx.x;
    int g = blockIdx.x;

    for (int i = t; i < 2000; i += 256) ((float4*)s_ws)[i] = ((const float4*)ws)[i];
    for (int i = t; i < 250;  i += 256) ((float4*)s_wt)[i] = ((const float4*)wt)[i];
    if (t < C_SZ) {
        float sc = gamma[t] * rsqrtf(var[t] + 1e-5f);
        float wr = wih[g*C_SZ + t];
        s_wr[t]  = wr;
        s_wsc[t] = wr * sc;
        s_shift[t] = beta[t] - mean[t]*sc;
        s_tb[t] = tb[t];
    }
    __syncthreads();

    if (t < C_SZ*E_SZ) {
        int cp = t / E_SZ, e = t % E_SZ;
        float s = 0.f;
        #pragma unroll 8
        for (int c = 0; c < C_SZ; c++) s += s_wsc[c] * s_ws[c*200 + cp*E_SZ + e];
        A_s[t] = s;
    }
    __syncthreads();

    if (t < KK) {
        int k = t / E_SZ, e = t % E_SZ;
        float s = 0.f;
        #pragma unroll 8
        for (int cp = 0; cp < C_SZ; cp++) s += A_s[cp*E_SZ + e] * s_wt[cp*25 + k];
        float w = s * (1.0f/25.0f);
        uint32_t bits = __float_as_uint(w);
        d_Wbfhi[g*136 + t] = (uint16_t)(bits >> 16);
        float lo = w - __uint_as_float(bits & 0xFFFF0000u);
        d_Wbflo[g*136 + t] = bf16_rn(lo);
    } else if (t < 136) {
        d_Wbfhi[g*136 + t] = 0;
        d_Wbflo[g*136 + t] = 0;
    }

    float part = 0.f;
    for (int idx = t; idx < 1600; idx += 256) {
        int c = idx / C_SZ, cp = idx % C_SZ;
        const float* w5 = &s_ws[c*200 + cp*E_SZ];
        float s5 = w5[0]+w5[1]+w5[2]+w5[3]+w5[4];
        part += s_wsc[c] * s_tb[cp] * s5;
    }
    if (t < C_SZ) part += s_wr[t] * s_shift[t];
    #pragma unroll
    for (int o = 16; o > 0; o >>= 1) part += __shfl_xor_sync(0xffffffffu, part, o);
    if ((t & 31) == 0) red[t >> 5] = part;
    __syncthreads();
    if (t == 0) {
        float s = red[0]+red[1]+red[2]+red[3]+red[4]+red[5]+red[6]+red[7];
        d_bg[g] = bih[g] + bhh[g] + s;
    }
}

// ============================================================
// Kernel 1 (FUSED): conv/pool/GEMM (tensor cores) + LSTM scan + FC.
// CTA = one batch element. Two 108-p half-passes reuse one
// XOR-swizzled A buffer; xg lives in SMEM; warp 0 scans at end.
// 256 thr, 111,968 B smem -> 2 CTAs/SM, 512 CTAs.
// ============================================================
#define CT 256
#define PHALF 108
// smem byte offsets
#define OB_WHI  0          // 10880 (stride 136 bf16, R12 layout)
#define OB_WLO  10880      // -> 21760
#define OB_BG   21760      // 160 -> 21952 (pad)
#define OB_XG   21952      // 216*40*4 = 34560 + 160 pad -> 56672
#define OB_AHI  56672      // 108*256 = 27648 -> 84320  (swizzled, stride 128 bf16)
#define OB_ALO  84320      // 27648 -> 111968
#define FUSED_SMEM_BYTES 111968

// swizzled A byte offset for (row pl, col kk): 16B chunk index (kk>>3) ^ (pl&7)
#define A_SWZ(pl, kk) ((uint32_t)((pl)*256 + ((((kk) >> 3) ^ ((pl) & 7)) << 4) + (((kk) & 7) << 1)))

__global__ void __launch_bounds__(CT) fused_kernel(
        const float* __restrict__ x,
        const float* __restrict__ whh,  // [40][10]
        const float* __restrict__ fcw,  // [2][10]
        const float* __restrict__ fcb,
        float* __restrict__ out)
{
    extern __shared__ char smc[];
    int tid  = threadIdx.x;
    int lane = tid & 31;
    int w    = tid >> 5;
    int b    = blockIdx.x;
    uint32_t sbase = smem_u32(smc);

    // stage weights + bias; zero A pad cols (kk 125..127, both arrays)
    {
        const uint4* ghi = (const uint4*)d_Wbfhi;
        const uint4* glo = (const uint4*)d_Wbflo;
        uint4* shi = (uint4*)(smc + OB_WHI);
        uint4* slo = (uint4*)(smc + OB_WLO);
        for (int i = tid; i < 680; i += CT) { shi[i] = ghi[i]; slo[i] = glo[i]; }
    }
    if (tid < G_SZ) ((float*)(smc + OB_BG))[tid] = d_bg[tid];
    for (int idx = tid; idx < PHALF*3; idx += CT) {
        int pl = idx / 3, kk = 125 + idx % 3;
        uint32_t off = A_SWZ(pl, kk);
        *(uint16_t*)(smc + OB_AHI + off) = 0;
        *(uint16_t*)(smc + OB_ALO + off) = 0;
    }
    __syncthreads();

    float* xgs = (float*)(smc + OB_XG);
    const float* xb0 = x + (size_t)b*(T_IN*E_SZ);

    for (int q = 0; q < 2; q++) {
        // ---- box sums straight from gmem into swizzled bf16 A hi/lo ----
        {
            int e = tid % 5, seg = tid / 5;      // seg 0..51 (tid 255 idle)
            int t0 = seg*11;
            if (t0 < 560) {
                const float* xq = xb0 + q*2700 + e;
                int t1 = min(t0+11, 560);
                float s = 0.f;
                #pragma unroll
                for (int j = 0; j < 25; j++) s += __ldg(xq + (t0+j)*5);
                for (int tt = t0; tt < t1; tt++) {
                    if (tt > t0) s += __ldg(xq + (tt+24)*5) - __ldg(xq + (tt-1)*5);
                    // split to bf16 hi/lo
                    uint32_t bits = __float_as_uint(s);
                    uint16_t hi = (uint16_t)(bits >> 16);
                    uint16_t lo = bf16_rn(s - __uint_as_float(bits & 0xFFFF0000u));
                    // value at flat f = tt*5+e -> A[pl][kk], pl = tt/5 - i, kk = (5*(tt%5)+e) + 25i
                    int qd = tt / 5, k0 = tt - 5*qd;
                    int kk0 = 5*k0 + e;
                    #pragma unroll
                    for (int i = 0; i < 5; i++) {
                        int pl = qd - i;
                        if (pl >= 0 && pl < PHALF) {
                            uint32_t off = A_SWZ(pl, kk0 + 25*i);
                            *(uint16_t*)(smc + OB_AHI + off) = hi;
                            *(uint16_t*)(smc + OB_ALO + off) = lo;
                        }
                    }
                }
            }
        }
        __syncthreads();

        // ---- MMA (R12 fragment logic; swizzled A addressing) ----
        if (w < 7) {
            int ar = 16*w + (lane & 15);
            int ar2 = min(ar, PHALF-1);          // rows 108..111 alias row 107 (discarded)
            uint32_t a8 = (uint32_t)(lane >> 4); // 0/1 -> k offset 0/8
            uint32_t arow_base = (uint32_t)(ar2*256);
            uint32_t apl7 = (uint32_t)(ar2 & 7);
            // B addresses (R12 verbatim, stride 136)
            int bl = lane & 15;
            uint32_t brow = (uint32_t)(bl & 7);
            uint32_t bk8  = (uint32_t)(((bl >> 3) & 1) * 8);

            float D[5][4];
            #pragma unroll
            for (int nt = 0; nt < 5; nt++)
                #pragma unroll
                for (int j = 0; j < 4; j++) D[nt][j] = 0.f;

            #pragma unroll
            for (int ks = 0; ks < 8; ks++) {
                uint32_t chunk = ((uint32_t)(2*ks) + a8) ^ apl7;
                uint32_t aoff = arow_base + (chunk << 4);
                uint32_t ahi[4], alo[4];
                ldsm_x4(ahi, sbase + OB_AHI + aoff);
                ldsm_x4(alo, sbase + OB_ALO + aoff);
                #pragma unroll
                for (int nt = 0; nt < 5; nt++) {
                    uint32_t boff = ((uint32_t)(nt*8) + brow)*272u + ((uint32_t)(ks*16) + bk8)*2u;
                    uint32_t bhi[2], blo[2];
                    ldsm_x2(bhi, sbase + OB_WHI + boff);
                    ldsm_x2(blo, sbase + OB_WLO + boff);
                    mma_bf16(D[nt], ahi, bhi);
                    mma_bf16(D[nt], ahi, blo);
                    mma_bf16(D[nt], alo, bhi);
                }
            }

            // epilogue: add bias, store xg tile to SMEM [t][g]
            const float* bgs = (const float*)(smc + OB_BG);
            int r0 = lane >> 2;
            int cp = (lane & 3) * 2;
            int p_a = 16*w + r0;
            int p_b = p_a + 8;
            float* dst = xgs + (size_t)(q*PHALF)*G_SZ;
            #pragma unroll
            for (int nt = 0; nt < 5; nt++) {
                int g = nt*8 + cp;
                float b0v = bgs[g], b1v = bgs[g+1];
                if (p_a < PHALF) {
                    float2 v = make_float2(D[nt][0] + b0v, D[nt][1] + b1v);
                    *(float2*)(dst + p_a*G_SZ + g) = v;
                }
                if (p_b < PHALF) {
                    float2 v = make_float2(D[nt][2] + b0v, D[nt][3] + b1v);
                    *(float2*)(dst + p_b*G_SZ + g) = v;
                }
            }
        }
        __syncthreads();
    }

    // ---- LSTM scan + FC (R11-proven; warp 0, lanes 0..9 own units) ----
    if (w == 0) {
        const float* xw = xgs;
        int r = min(lane, 9);
        float wi[H_SZ], wf[H_SZ], wg[H_SZ], wo[H_SZ];
        #pragma unroll
        for (int j = 0; j < H_SZ; j++) {
            wi[j] = whh[(r     )*H_SZ + j];
            wf[j] = whh[(r + 10)*H_SZ + j];
            wg[j] = whh[(r + 20)*H_SZ + j];
            wo[j] = whh[(r + 30)*H_SZ + j];
        }

        float h[H_SZ];
        #pragma unroll
        for (int j = 0; j < H_SZ; j++) h[j] = 0.f;
        float c = 0.f;

        float ci = xw[r], cf = xw[10+r], cg = xw[20+r], co = xw[30+r];
        for (int t = 0; t < L_SZ; t++) {
            const float* nx = xw + (t+1)*G_SZ;     // t=215 overruns into 160B pad
            float ni = nx[r], nf = nx[10+r], ng = nx[20+r], no = nx[30+r];

            float ia = ci, ib = 0.f, fa = cf, fb = 0.f;
            float ga = cg, gb = 0.f, oa = co, ob = 0.f;
            #pragma unroll
            for (int j = 0; j < 5; j++) {
                ia = fmaf(wi[j], h[j], ia);  ib = fmaf(wi[j+5], h[j+5], ib);
                fa = fmaf(wf[j], h[j], fa);  fb = fmaf(wf[j+5], h[j+5], fb);
                ga = fmaf(wg[j], h[j], ga);  gb = fmaf(wg[j+5], h[j+5], gb);
                oa = fmaf(wo[j], h[j], oa);  ob = fmaf(wo[j+5], h[j+5], ob);
            }
            float iv = fmaf(0.5f, tanh_a(0.5f*(ia+ib)), 0.5f);
            float fv = fmaf(0.5f, tanh_a(0.5f*(fa+fb)), 0.5f);
            float gv = tanh_a(ga+gb);
            float ov = fmaf(0.5f, tanh_a(0.5f*(oa+ob)), 0.5f);
            c = fmaf(fv, c, iv*gv);
            float hv = ov * tanh_a(c);
            #pragma unroll
            for (int j = 0; j < H_SZ; j++)
                h[j] = __shfl_sync(0xffffffffu, hv, j);
            ci = ni; cf = nf; cg = ng; co = no;
        }

        if (lane < 2) {
            float o = fcb[lane];
            #pragma unroll
            for (int j = 0; j < H_SZ; j++) o = fmaf(fcw[lane*H_SZ + j], h[j], o);
            out[b*2 + lane] = o;
        }
    }
}

// ============================================================
extern "C" void kernel_launch(void* const* d_in, const int* in_sizes, int n_in,
                              void* d_out, int out_size)
{
    const float* x     = (const float*)d_in[0];
    const float* ctw   = (const float*)d_in[1];
    const float* ctb   = (const float*)d_in[2];
    const float* csw   = (const float*)d_in[3];
    const float* gamma = (const float*)d_in[4];
    const float* beta  = (const float*)d_in[5];
    const float* mean  = (const float*)d_in[6];
    const float* var   = (const float*)d_in[7];
    const float* wih   = (const float*)d_in[8];
    const float* whh   = (const float*)d_in[9];
    const float* bih   = (const float*)d_in[10];
    const float* bhh   = (const float*)d_in[11];
    const float* fcw   = (const float*)d_in[12];
    const float* fcb   = (const float*)d_in[13];
    float* out = (float*)d_out;

    cudaFuncSetAttribute(fused_kernel, cudaFuncAttributeMaxDynamicSharedMemorySize, FUSED_SMEM_BYTES);

    prep_kernel<<<G_SZ, 256>>>(ctw, ctb, csw, gamma, beta, mean, var, wih, bih, bhh);
    fused_kernel<<<B_SZ, CT, FUSED_SMEM_BYTES>>>(x, whh, fcw, fcb, out);
}

// round 14
// speedup vs baseline: 1.3802x; 1.3802x over previous
#include <cuda_runtime.h>
#include <cuda_bf16.h>
#include <math.h>
#include <cstdint>

// Problem dims
#define B_SZ 512
#define T_IN 1125
#define E_SZ 5
#define C_SZ 40
#define L_SZ 216
#define G_SZ 40
#define H_SZ 10
#define KK   125

// ---- persistent scratch ----
__device__ __align__(16) float d_bg[G_SZ];
__device__ __align__(16) float d_xg[B_SZ*L_SZ*G_SZ];    // [b][t][g]
__device__ __align__(16) uint16_t d_Wbfhi[G_SZ*128];    // bf16 W[n][k], SWIZZLED stride 128
__device__ __align__(16) uint16_t d_Wbflo[G_SZ*128];

// swizzled byte offset for (row, col) in a stride-128-bf16 image:
// 16B chunk index (col>>3) ^ (row&7)
#define SWZ_OFF(row, col) ((uint32_t)((row)*256 + (((((col) >> 3)) ^ ((row) & 7)) << 4) + (((col) & 7) << 1)))

__device__ __forceinline__ float tanh_a(float x) {
    float r; asm("tanh.approx.f32 %0, %1;" : "=f"(r) : "f"(x)); return r;
}
__device__ __forceinline__ uint32_t smem_u32(const void* p) {
    uint32_t a;
    asm("{ .reg .u64 t; cvta.to.shared.u64 t, %1; cvt.u32.u64 %0, t; }" : "=r"(a) : "l"(p));
    return a;
}
__device__ __forceinline__ void ldsm_x4(uint32_t* r, uint32_t addr) {
    asm volatile("ldmatrix.sync.aligned.m8n8.x4.shared.b16 {%0,%1,%2,%3}, [%4];"
        : "=r"(r[0]), "=r"(r[1]), "=r"(r[2]), "=r"(r[3]) : "r"(addr));
}
__device__ __forceinline__ void ldsm_x2(uint32_t* r, uint32_t addr) {
    asm volatile("ldmatrix.sync.aligned.m8n8.x2.shared.b16 {%0,%1}, [%2];"
        : "=r"(r[0]), "=r"(r[1]) : "r"(addr));
}
__device__ __forceinline__ void mma_bf16(float* d, const uint32_t* a, const uint32_t* b) {
    asm volatile("mma.sync.aligned.m16n8k16.row.col.f32.bf16.bf16.f32 "
        "{%0,%1,%2,%3}, {%4,%5,%6,%7}, {%8,%9}, {%0,%1,%2,%3};"
        : "+f"(d[0]), "+f"(d[1]), "+f"(d[2]), "+f"(d[3])
        : "r"(a[0]), "r"(a[1]), "r"(a[2]), "r"(a[3]), "r"(b[0]), "r"(b[1]));
}
__device__ __forceinline__ uint16_t bf16_rn(float v) {
    __nv_bfloat16 h = __float2bfloat16(v);
    return *reinterpret_cast<uint16_t*>(&h);
}

// ============================================================
// Kernel 0: weight fold -> SWIZZLED bf16 hi/lo images + bg[40].
// (R12 math verbatim; only the store addressing changed)
// ============================================================
__global__ void __launch_bounds__(256) prep_kernel(
        const float* __restrict__ wt,     // [40][25]
        const float* __restrict__ tb,     // [40]
        const float* __restrict__ ws,     // [40][40][5]
        const float* __restrict__ gamma,
        const float* __restrict__ beta,
        const float* __restrict__ mean,
        const float* __restrict__ var,
        const float* __restrict__ wih,    // [40][40]
        const float* __restrict__ bih,
        const float* __restrict__ bhh)
{
    __shared__ __align__(16) float s_ws[C_SZ*C_SZ*E_SZ];   // 8000
    __shared__ __align__(16) float s_wt[C_SZ*25];
    __shared__ float s_wr[C_SZ], s_wsc[C_SZ], s_shift[C_SZ], s_tb[C_SZ];
    __shared__ float A_s[C_SZ*E_SZ];
    __shared__ float red[8];
    int t = threadIdx.x;
    int g = blockIdx.x;

    for (int i = t; i < 2000; i += 256) ((float4*)s_ws)[i] = ((const float4*)ws)[i];
    for (int i = t; i < 250;  i += 256) ((float4*)s_wt)[i] = ((const float4*)wt)[i];
    if (t < C_SZ) {
        float sc = gamma[t] * rsqrtf(var[t] + 1e-5f);
        float wr = wih[g*C_SZ + t];
        s_wr[t]  = wr;
        s_wsc[t] = wr * sc;
        s_shift[t] = beta[t] - mean[t]*sc;
        s_tb[t] = tb[t];
    }
    __syncthreads();

    if (t < C_SZ*E_SZ) {
        int cp = t / E_SZ, e = t % E_SZ;
        float s = 0.f;
        #pragma unroll 8
        for (int c = 0; c < C_SZ; c++) s += s_wsc[c] * s_ws[c*200 + cp*E_SZ + e];
        A_s[t] = s;
    }
    __syncthreads();

    if (t < KK) {
        int k = t / E_SZ, e = t % E_SZ;
        float s = 0.f;
        #pragma unroll 8
        for (int cp = 0; cp < C_SZ; cp++) s += A_s[cp*E_SZ + e] * s_wt[cp*25 + k];
        float w = s * (1.0f/25.0f);
        uint32_t bits = __float_as_uint(w);
        *(uint16_t*)((char*)d_Wbfhi + SWZ_OFF(g, t)) = (uint16_t)(bits >> 16);
        float lo = w - __uint_as_float(bits & 0xFFFF0000u);
        *(uint16_t*)((char*)d_Wbflo + SWZ_OFF(g, t)) = bf16_rn(lo);
    } else if (t < 128) {
        *(uint16_t*)((char*)d_Wbfhi + SWZ_OFF(g, t)) = 0;
        *(uint16_t*)((char*)d_Wbflo + SWZ_OFF(g, t)) = 0;
    }

    float part = 0.f;
    for (int idx = t; idx < 1600; idx += 256) {
        int c = idx / C_SZ, cp = idx % C_SZ;
        const float* w5 = &s_ws[c*200 + cp*E_SZ];
        float s5 = w5[0]+w5[1]+w5[2]+w5[3]+w5[4];
        part += s_wsc[c] * s_tb[cp] * s5;
    }
    if (t < C_SZ) part += s_wr[t] * s_shift[t];
    #pragma unroll
    for (int o = 16; o > 0; o >>= 1) part += __shfl_xor_sync(0xffffffffu, part, o);
    if ((t & 31) == 0) red[t >> 5] = part;
    __syncthreads();
    if (t == 0) {
        float s = red[0]+red[1]+red[2]+red[3]+red[4]+red[5]+red[6]+red[7];
        d_bg[g] = bih[g] + bhh[g] + s;
    }
}

// ============================================================
// Kernel 1: conv/pool/GEMM (tensor cores, hi/lo split).
// SMEM DIET: swizzled W (20.5KB) + swizzled A (2x27KB), gmem-
// direct box sums (no x slab, no Bsum). 76,032 B -> 3 CTAs/SM.
// ============================================================
#define CT 256
#define PHALF 108
// smem byte offsets
#define OB_WHI  0          // 10240
#define OB_WLO  10240      // -> 20480
#define OB_BG   20480      // 160 -> 20736 (pad)
#define OB_AHI  20736      // 108*256 = 27648 -> 48384
#define OB_ALO  48384      // 27648 -> 76032
#define CONV_SMEM_BYTES 76032

__global__ void __launch_bounds__(CT) conv_kernel(const float* __restrict__ x)
{
    extern __shared__ char smc[];
    int tid  = threadIdx.x;
    int lane = tid & 31;
    int w    = tid >> 5;
    int q    = blockIdx.x;             // 0/1 -> p [0,108) / [108,216)
    int b    = blockIdx.y;
    uint32_t sbase = smem_u32(smc);

    // stage weights (already swizzled in gmem -> straight copy) + bias
    {
        const uint4* ghi = (const uint4*)d_Wbfhi;
        const uint4* glo = (const uint4*)d_Wbflo;
        uint4* shi = (uint4*)(smc + OB_WHI);
        uint4* slo = (uint4*)(smc + OB_WLO);
        for (int i = tid; i < 640; i += CT) { shi[i] = ghi[i]; slo[i] = glo[i]; }
    }
    if (tid < G_SZ) ((float*)(smc + OB_BG))[tid] = d_bg[tid];
    // zero A pad cols kk 125..127
    for (int idx = tid; idx < PHALF*3; idx += CT) {
        int pl = idx / 3, kk = 125 + idx % 3;
        uint32_t off = SWZ_OFF(pl, kk);
        *(uint16_t*)(smc + OB_AHI + off) = 0;
        *(uint16_t*)(smc + OB_ALO + off) = 0;
    }
    __syncthreads();

    // gmem-direct box sums -> swizzled bf16 A hi/lo (R13-proven)
    {
        int e = tid % 5, seg = tid / 5;      // seg 0..51 (tid 255 idle)
        int t0 = seg*11;
        if (t0 < 560) {
            const float* xq = x + (size_t)b*(T_IN*E_SZ) + q*2700 + e;
            int t1 = min(t0+11, 560);
            float s = 0.f;
            #pragma unroll
            for (int j = 0; j < 25; j++) s += __ldg(xq + (t0+j)*5);
            for (int tt = t0; tt < t1; tt++) {
                if (tt > t0) s += __ldg(xq + (tt+24)*5) - __ldg(xq + (tt-1)*5);
                uint32_t bits = __float_as_uint(s);
                uint16_t hi = (uint16_t)(bits >> 16);
                uint16_t lo = bf16_rn(s - __uint_as_float(bits & 0xFFFF0000u));
                int qd = tt / 5, k0 = tt - 5*qd;
                int kk0 = 5*k0 + e;
                #pragma unroll
                for (int i = 0; i < 5; i++) {
                    int pl = qd - i;
                    if (pl >= 0 && pl < PHALF) {
                        uint32_t off = SWZ_OFF(pl, kk0 + 25*i);
                        *(uint16_t*)(smc + OB_AHI + off) = hi;
                        *(uint16_t*)(smc + OB_ALO + off) = lo;
                    }
                }
            }
        }
    }
    __syncthreads();

    // MMA: 7 warps, warp w -> rows 16w..16w+15 (rows >=108 clamp to 107, discarded)
    if (w < 7) {
        int ar = 16*w + (lane & 15);
        int ar2 = min(ar, PHALF-1);
        uint32_t a8 = (uint32_t)(lane >> 4);
        uint32_t arow_base = (uint32_t)(ar2*256);
        uint32_t apl7 = (uint32_t)(ar2 & 7);
        int bl = lane & 15;
        uint32_t brow = (uint32_t)(bl & 7);
        uint32_t bsel = (uint32_t)((bl >> 3) & 1);

        float D[5][4];
        #pragma unroll
        for (int nt = 0; nt < 5; nt++)
            #pragma unroll
            for (int j = 0; j < 4; j++) D[nt][j] = 0.f;

        #pragma unroll
        for (int ks = 0; ks < 8; ks++) {
            uint32_t achunk = ((uint32_t)(2*ks) + a8) ^ apl7;
            uint32_t aoff = arow_base + (achunk << 4);
            uint32_t ahi[4], alo[4];
            ldsm_x4(ahi, sbase + OB_AHI + aoff);
            ldsm_x4(alo, sbase + OB_ALO + aoff);
            uint32_t bchunk = ((uint32_t)(2*ks) + bsel) ^ brow;
            #pragma unroll
            for (int nt = 0; nt < 5; nt++) {
                uint32_t boff = ((uint32_t)(nt*8) + brow)*256u + (bchunk << 4);
                uint32_t bhi[2], blo[2];
                ldsm_x2(bhi, sbase + OB_WHI + boff);
                ldsm_x2(blo, sbase + OB_WLO + boff);
                mma_bf16(D[nt], ahi, bhi);
                mma_bf16(D[nt], ahi, blo);
                mma_bf16(D[nt], alo, bhi);
            }
        }

        // epilogue: add bias, store [b][t][g]
        const float* bgs = (const float*)(smc + OB_BG);
        int r0 = lane >> 2;
        int cp = (lane & 3) * 2;
        float* dst = d_xg + (size_t)b*(L_SZ*G_SZ) + (size_t)(q*PHALF)*G_SZ;
        int p_a = 16*w + r0;
        int p_b = p_a + 8;
        #pragma unroll
        for (int nt = 0; nt < 5; nt++) {
            int g = nt*8 + cp;
            float b0v = bgs[g], b1v = bgs[g+1];
            if (p_a < PHALF) {
                float2 v = make_float2(D[nt][0] + b0v, D[nt][1] + b1v);
                *(float2*)(dst + p_a*G_SZ + g) = v;
            }
            if (p_b < PHALF) {
                float2 v = make_float2(D[nt][2] + b0v, D[nt][3] + b1v);
                *(float2*)(dst + p_b*G_SZ + g) = v;
            }
        }
    }
}

// ============================================================
// Kernel 2: LSTM scan + FC (R12 verbatim — proven).
// ============================================================
#define LSTM_WARPS 4
#define XSLICE_FLOATS (L_SZ*G_SZ)            // 8640
#define XSLICE_BYTES  (XSLICE_FLOATS*4)      // 34560
#define LSTM_SMEM_BYTES (LSTM_WARPS*XSLICE_BYTES + 256)

__global__ void __launch_bounds__(32*LSTM_WARPS) lstm_kernel(
        const float* __restrict__ whh,  // [40][10]
        const float* __restrict__ fcw,  // [2][10]
        const float* __restrict__ fcb,
        float* __restrict__ out)
{
    extern __shared__ float xsm[];
    int warp = threadIdx.x >> 5;
    int lid  = threadIdx.x & 31;
    int b    = blockIdx.x*LSTM_WARPS + warp;

    {
        uint32_t dst0 = smem_u32(xsm) + warp*XSLICE_BYTES;
        const char* src0 = (const char*)(d_xg + (size_t)b*XSLICE_FLOATS);
        for (int c = lid; c < 2160; c += 32) {
            asm volatile("cp.async.ca.shared.global [%0], [%1], 16;"
                         :: "r"(dst0 + (uint32_t)(c*16)), "l"(src0 + (size_t)c*16));
        }
        asm volatile("cp.async.commit_group;" ::: "memory");
        asm volatile("cp.async.wait_group 0;" ::: "memory");
        __syncwarp();
    }
    const float* xw = xsm + warp*XSLICE_FLOATS;

    int r = min(lid, 9);
    float wi[H_SZ], wf[H_SZ], wg[H_SZ], wo[H_SZ];
    #pragma unroll
    for (int j = 0; j < H_SZ; j++) {
        wi[j] = whh[(r     )*H_SZ + j];
        wf[j] = whh[(r + 10)*H_SZ + j];
        wg[j] = whh[(r + 20)*H_SZ + j];
        wo[j] = whh[(r + 30)*H_SZ + j];
    }

    float h[H_SZ];
    #pragma unroll
    for (int j = 0; j < H_SZ; j++) h[j] = 0.f;
    float c = 0.f;

    float ci = xw[r], cf = xw[10+r], cg = xw[20+r], co = xw[30+r];
    for (int t = 0; t < L_SZ; t++) {
        const float* nx = xw + (t+1)*G_SZ;     // t=215 overruns into pad
        float ni = nx[r], nf = nx[10+r], ng = nx[20+r], no = nx[30+r];

        float ia = ci, ib = 0.f, fa = cf, fb = 0.f;
        float ga = cg, gb = 0.f, oa = co, ob = 0.f;
        #pragma unroll
        for (int j = 0; j < 5; j++) {
            ia = fmaf(wi[j], h[j], ia);  ib = fmaf(wi[j+5], h[j+5], ib);
            fa = fmaf(wf[j], h[j], fa);  fb = fmaf(wf[j+5], h[j+5], fb);
            ga = fmaf(wg[j], h[j], ga);  gb = fmaf(wg[j+5], h[j+5], gb);
            oa = fmaf(wo[j], h[j], oa);  ob = fmaf(wo[j+5], h[j+5], ob);
        }
        float iv = fmaf(0.5f, tanh_a(0.5f*(ia+ib)), 0.5f);
        float fv = fmaf(0.5f, tanh_a(0.5f*(fa+fb)), 0.5f);
        float gv = tanh_a(ga+gb);
        float ov = fmaf(0.5f, tanh_a(0.5f*(oa+ob)), 0.5f);
        c = fmaf(fv, c, iv*gv);
        float hv = ov * tanh_a(c);
        #pragma unroll
        for (int j = 0; j < H_SZ; j++)
            h[j] = __shfl_sync(0xffffffffu, hv, j);
        ci = ni; cf = nf; cg = ng; co = no;
    }

    if (lid < 2) {
        float o = fcb[lid];
        #pragma unroll
        for (int j = 0; j < H_SZ; j++) o = fmaf(fcw[lid*H_SZ + j], h[j], o);
        out[b*2 + lid] = o;
    }
}

// ============================================================
extern "C" void kernel_launch(void* const* d_in, const int* in_sizes, int n_in,
                              void* d_out, int out_size)
{
    const float* x     = (const float*)d_in[0];
    const float* ctw   = (const float*)d_in[1];
    const float* ctb   = (const float*)d_in[2];
    const float* csw   = (const float*)d_in[3];
    const float* gamma = (const float*)d_in[4];
    const float* beta  = (const float*)d_in[5];
    const float* mean  = (const float*)d_in[6];
    const float* var   = (const float*)d_in[7];
    const float* wih   = (const float*)d_in[8];
    const float* whh   = (const float*)d_in[9];
    const float* bih   = (const float*)d_in[10];
    const float* bhh   = (const float*)d_in[11];
    const float* fcw   = (const float*)d_in[12];
    const float* fcb   = (const float*)d_in[13];
    float* out = (float*)d_out;

    cudaFuncSetAttribute(conv_kernel, cudaFuncAttributeMaxDynamicSharedMemorySize, CONV_SMEM_BYTES);
    cudaFuncSetAttribute(lstm_kernel, cudaFuncAttributeMaxDynamicSharedMemorySize, LSTM_SMEM_BYTES);

    prep_kernel<<<G_SZ, 256>>>(ctw, ctb, csw, gamma, beta, mean, var, wih, bih, bhh);
    conv_kernel<<<dim3(2, B_SZ), CT, CONV_SMEM_BYTES>>>(x);
    lstm_kernel<<<B_SZ/LSTM_WARPS, 32*LSTM_WARPS, LSTM_SMEM_BYTES>>>(whh, fcw, fcb, out);
}

// round 15
// speedup vs baseline: 1.5321x; 1.1101x over previous
#include <cuda_runtime.h>
#include <cuda_bf16.h>
#include <math.h>
#include <cstdint>

// Problem dims
#define B_SZ 512
#define T_IN 1125
#define E_SZ 5
#define C_SZ 40
#define L_SZ 216
#define G_SZ 40
#define H_SZ 10
#define KK   125

// ---- persistent scratch ----
__device__ __align__(16) float d_bg[G_SZ];
__device__ __align__(16) float d_xg[B_SZ*L_SZ*G_SZ];    // [b][t][g]
__device__ __align__(16) uint16_t d_Wbfhi[G_SZ*128];    // bf16 W[n][kk'], SWIZZLED stride 128
__device__ __align__(16) uint16_t d_Wbflo[G_SZ*128];    // kk' = e*25 + k reordering

// swizzled byte offset for (row, col) in a stride-128-bf16 image
#define SWZ_OFF(row, col) ((uint32_t)((row)*256 + (((((col) >> 3)) ^ ((row) & 7)) << 4) + (((col) & 7) << 1)))

__device__ __forceinline__ float tanh_a(float x) {
    float r; asm("tanh.approx.f32 %0, %1;" : "=f"(r) : "f"(x)); return r;
}
__device__ __forceinline__ uint32_t smem_u32(const void* p) {
    uint32_t a;
    asm("{ .reg .u64 t; cvta.to.shared.u64 t, %1; cvt.u32.u64 %0, t; }" : "=r"(a) : "l"(p));
    return a;
}
__device__ __forceinline__ void ldsm_x4(uint32_t* r, uint32_t addr) {
    asm volatile("ldmatrix.sync.aligned.m8n8.x4.shared.b16 {%0,%1,%2,%3}, [%4];"
        : "=r"(r[0]), "=r"(r[1]), "=r"(r[2]), "=r"(r[3]) : "r"(addr));
}
__device__ __forceinline__ void ldsm_x2(uint32_t* r, uint32_t addr) {
    asm volatile("ldmatrix.sync.aligned.m8n8.x2.shared.b16 {%0,%1}, [%2];"
        : "=r"(r[0]), "=r"(r[1]) : "r"(addr));
}
__device__ __forceinline__ void mma_bf16(float* d, const uint32_t* a, const uint32_t* b) {
    asm volatile("mma.sync.aligned.m16n8k16.row.col.f32.bf16.bf16.f32 "
        "{%0,%1,%2,%3}, {%4,%5,%6,%7}, {%8,%9}, {%0,%1,%2,%3};"
        : "+f"(d[0]), "+f"(d[1]), "+f"(d[2]), "+f"(d[3])
        : "r"(a[0]), "r"(a[1]), "r"(a[2]), "r"(a[3]), "r"(b[0]), "r"(b[1]));
}
__device__ __forceinline__ uint16_t bf16_rn(float v) {
    __nv_bfloat16 h = __float2bfloat16(v);
    return *reinterpret_cast<uint16_t*>(&h);
}

// ============================================================
// Kernel 0: weight fold -> SWIZZLED bf16 hi/lo images + bg[40].
// (R14 math verbatim; W stored at reordered column kk' = e*25+k)
// ============================================================
__global__ void __launch_bounds__(256) prep_kernel(
        const float* __restrict__ wt,     // [40][25]
        const float* __restrict__ tb,     // [40]
        const float* __restrict__ ws,     // [40][40][5]
        const float* __restrict__ gamma,
        const float* __restrict__ beta,
        const float* __restrict__ mean,
        const float* __restrict__ var,
        const float* __restrict__ wih,    // [40][40]
        const float* __restrict__ bih,
        const float* __restrict__ bhh)
{
    __shared__ __align__(16) float s_ws[C_SZ*C_SZ*E_SZ];   // 8000
    __shared__ __align__(16) float s_wt[C_SZ*25];
    __shared__ float s_wr[C_SZ], s_wsc[C_SZ], s_shift[C_SZ], s_tb[C_SZ];
    __shared__ float A_s[C_SZ*E_SZ];
    __shared__ float red[8];
    int t = threadIdx.x;
    int g = blockIdx.x;

    for (int i = t; i < 2000; i += 256) ((float4*)s_ws)[i] = ((const float4*)ws)[i];
    for (int i = t; i < 250;  i += 256) ((float4*)s_wt)[i] = ((const float4*)wt)[i];
    if (t < C_SZ) {
        float sc = gamma[t] * rsqrtf(var[t] + 1e-5f);
        float wr = wih[g*C_SZ + t];
        s_wr[t]  = wr;
        s_wsc[t] = wr * sc;
        s_shift[t] = beta[t] - mean[t]*sc;
        s_tb[t] = tb[t];
    }
    __syncthreads();

    if (t < C_SZ*E_SZ) {
        int cp = t / E_SZ, e = t % E_SZ;
        float s = 0.f;
        #pragma unroll 8
        for (int c = 0; c < C_SZ; c++) s += s_wsc[c] * s_ws[c*200 + cp*E_SZ + e];
        A_s[t] = s;
    }
    __syncthreads();

    if (t < KK) {
        int k = t / E_SZ, e = t % E_SZ;
        float s = 0.f;
        #pragma unroll 8
        for (int cp = 0; cp < C_SZ; cp++) s += A_s[cp*E_SZ + e] * s_wt[cp*25 + k];
        float w = s * (1.0f/25.0f);
        int col = e*25 + k;                 // reordered kk'
        uint32_t bits = __float_as_uint(w);
        *(uint16_t*)((char*)d_Wbfhi + SWZ_OFF(g, col)) = (uint16_t)(bits >> 16);
        float lo = w - __uint_as_float(bits & 0xFFFF0000u);
        *(uint16_t*)((char*)d_Wbflo + SWZ_OFF(g, col)) = bf16_rn(lo);
    } else if (t < 128) {
        *(uint16_t*)((char*)d_Wbfhi + SWZ_OFF(g, t)) = 0;
        *(uint16_t*)((char*)d_Wbflo + SWZ_OFF(g, t)) = 0;
    }

    float part = 0.f;
    for (int idx = t; idx < 1600; idx += 256) {
        int c = idx / C_SZ, cp = idx % C_SZ;
        const float* w5 = &s_ws[c*200 + cp*E_SZ];
        float s5 = w5[0]+w5[1]+w5[2]+w5[3]+w5[4];
        part += s_wsc[c] * s_tb[cp] * s5;
    }
    if (t < C_SZ) part += s_wr[t] * s_shift[t];
    #pragma unroll
    for (int o = 16; o > 0; o >>= 1) part += __shfl_xor_sync(0xffffffffu, part, o);
    if ((t & 31) == 0) red[t >> 5] = part;
    __syncthreads();
    if (t == 0) {
        float s = red[0]+red[1]+red[2]+red[3]+red[4]+red[5]+red[6]+red[7];
        d_bg[g] = bih[g] + bhh[g] + s;
    }
}

// ============================================================
// Kernel 1: conv/pool/GEMM (tensor cores, hi/lo split).
// kk' = e*25+k reorder -> A rows contiguous in Bsum[e][t]:
//   Phase A: box sums -> Bsum (fp32, aliased in W region)
//   Phase B: vectorized pack (STS.128) -> swizzled Ahi/Alo
//   Phase C: stage W (overwrites Bsum) + bias
//   Phase D: MMA (R14 verbatim)
// 76,032 B smem -> 3 CTAs/SM.
// ============================================================
#define CT 256
#define PHALF 108
// smem byte offsets
#define OB_WHI  0          // 10240  (Bsum 11200B aliases [0, 11200) in phases A-B)
#define OB_WLO  10240      // -> 20480
#define OB_BG   20480      // 160 -> 20736 (pad)
#define OB_AHI  20736      // 108*256 = 27648 -> 48384
#define OB_ALO  48384      // 27648 -> 76032
#define CONV_SMEM_BYTES 76032

__global__ void __launch_bounds__(CT) conv_kernel(const float* __restrict__ x)
{
    extern __shared__ char smc[];
    int tid  = threadIdx.x;
    int lane = tid & 31;
    int w    = tid >> 5;
    int q    = blockIdx.x;             // 0/1 -> p [0,108) / [108,216)
    int b    = blockIdx.y;
    uint32_t sbase = smem_u32(smc);

    // ---- Phase A: box sums -> Bsum[e][560] (fp32, in W region) ----
    float* Bsum = (float*)smc;
    {
        int e = tid % 5, seg = tid / 5;      // seg 0..50 (tid 255 idle)
        int t0 = seg*11;
        if (t0 < 560) {
            const float* xq = x + (size_t)b*(T_IN*E_SZ) + q*2700 + e;
            int t1 = min(t0+11, 560);
            float s = 0.f;
            #pragma unroll
            for (int j = 0; j < 25; j++) s += __ldg(xq + (t0+j)*5);
            Bsum[e*560 + t0] = s;
            for (int tt = t0+1; tt < t1; tt++) {
                s += __ldg(xq + (tt+24)*5) - __ldg(xq + (tt-1)*5);
                Bsum[e*560 + tt] = s;
            }
        }
    }
    __syncthreads();

    // ---- Phase B: vectorized pack -> swizzled Ahi/Alo ----
    // task = (pl, chunk c): kk = 8c..8c+7, val = Bsum[kk/25][5pl + kk%25]
    for (int task = tid; task < PHALF*16; task += CT) {
        int pl = task >> 4;
        int c  = task & 15;
        float v[8];
        #pragma unroll
        for (int j = 0; j < 8; j++) {
            int kk = 8*c + j;
            int e  = kk / 25;
            int k  = kk - 25*e;
            v[j] = (kk < KK) ? Bsum[e*560 + 5*pl + k] : 0.f;
        }
        uint32_t hi[4], lo[4];
        #pragma unroll
        for (int j = 0; j < 4; j++) {
            uint32_t b0 = __float_as_uint(v[2*j]);
            uint32_t b1 = __float_as_uint(v[2*j+1]);
            hi[j] = __byte_perm(b0, b1, 0x7632);
            float l0 = v[2*j]   - __uint_as_float(b0 & 0xFFFF0000u);
            float l1 = v[2*j+1] - __uint_as_float(b1 & 0xFFFF0000u);
            asm("cvt.rn.bf16x2.f32 %0, %1, %2;" : "=r"(lo[j]) : "f"(l1), "f"(l0));
        }
        uint32_t off = (uint32_t)(pl*256 + (((c) ^ (pl & 7)) << 4));
        *(uint4*)(smc + OB_AHI + off) = make_uint4(hi[0], hi[1], hi[2], hi[3]);
        *(uint4*)(smc + OB_ALO + off) = make_uint4(lo[0], lo[1], lo[2], lo[3]);
    }
    __syncthreads();

    // ---- Phase C: stage W (overwrite Bsum region) + bias ----
    {
        const uint4* ghi = (const uint4*)d_Wbfhi;
        const uint4* glo = (const uint4*)d_Wbflo;
        uint4* shi = (uint4*)(smc + OB_WHI);
        uint4* slo = (uint4*)(smc + OB_WLO);
        for (int i = tid; i < 640; i += CT) { shi[i] = ghi[i]; slo[i] = glo[i]; }
    }
    if (tid < G_SZ) ((float*)(smc + OB_BG))[tid] = d_bg[tid];
    __syncthreads();

    // ---- Phase D: MMA (R14 verbatim) ----
    if (w < 7) {
        int ar = 16*w + (lane & 15);
        int ar2 = min(ar, PHALF-1);
        uint32_t a8 = (uint32_t)(lane >> 4);
        uint32_t arow_base = (uint32_t)(ar2*256);
        uint32_t apl7 = (uint32_t)(ar2 & 7);
        int bl = lane & 15;
        uint32_t brow = (uint32_t)(bl & 7);
        uint32_t bsel = (uint32_t)((bl >> 3) & 1);

        float D[5][4];
        #pragma unroll
        for (int nt = 0; nt < 5; nt++)
            #pragma unroll
            for (int j = 0; j < 4; j++) D[nt][j] = 0.f;

        #pragma unroll
        for (int ks = 0; ks < 8; ks++) {
            uint32_t achunk = ((uint32_t)(2*ks) + a8) ^ apl7;
            uint32_t aoff = arow_base + (achunk << 4);
            uint32_t ahi[4], alo[4];
            ldsm_x4(ahi, sbase + OB_AHI + aoff);
            ldsm_x4(alo, sbase + OB_ALO + aoff);
            uint32_t bchunk = ((uint32_t)(2*ks) + bsel) ^ brow;
            #pragma unroll
            for (int nt = 0; nt < 5; nt++) {
                uint32_t boff = ((uint32_t)(nt*8) + brow)*256u + (bchunk << 4);
                uint32_t bhi[2], blo[2];
                ldsm_x2(bhi, sbase + OB_WHI + boff);
                ldsm_x2(blo, sbase + OB_WLO + boff);
                mma_bf16(D[nt], ahi, bhi);
                mma_bf16(D[nt], ahi, blo);
                mma_bf16(D[nt], alo, bhi);
            }
        }

        // epilogue: add bias, store [b][t][g]
        const float* bgs = (const float*)(smc + OB_BG);
        int r0 = lane >> 2;
        int cp = (lane & 3) * 2;
        float* dst = d_xg + (size_t)b*(L_SZ*G_SZ) + (size_t)(q*PHALF)*G_SZ;
        int p_a = 16*w + r0;
        int p_b = p_a + 8;
        #pragma unroll
        for (int nt = 0; nt < 5; nt++) {
            int g = nt*8 + cp;
            float b0v = bgs[g], b1v = bgs[g+1];
            if (p_a < PHALF) {
                float2 v = make_float2(D[nt][0] + b0v, D[nt][1] + b1v);
                *(float2*)(dst + p_a*G_SZ + g) = v;
            }
            if (p_b < PHALF) {
                float2 v = make_float2(D[nt][2] + b0v, D[nt][3] + b1v);
                *(float2*)(dst + p_b*G_SZ + g) = v;
            }
        }
    }
}

// ============================================================
// Kernel 2: LSTM scan + FC (R14 verbatim — proven).
// ============================================================
#define LSTM_WARPS 4
#define XSLICE_FLOATS (L_SZ*G_SZ)            // 8640
#define XSLICE_BYTES  (XSLICE_FLOATS*4)      // 34560
#define LSTM_SMEM_BYTES (LSTM_WARPS*XSLICE_BYTES + 256)

__global__ void __launch_bounds__(32*LSTM_WARPS) lstm_kernel(
        const float* __restrict__ whh,  // [40][10]
        const float* __restrict__ fcw,  // [2][10]
        const float* __restrict__ fcb,
        float* __restrict__ out)
{
    extern __shared__ float xsm[];
    int warp = threadIdx.x >> 5;
    int lid  = threadIdx.x & 31;
    int b    = blockIdx.x*LSTM_WARPS + warp;

    {
        uint32_t dst0 = smem_u32(xsm) + warp*XSLICE_BYTES;
        const char* src0 = (const char*)(d_xg + (size_t)b*XSLICE_FLOATS);
        for (int c = lid; c < 2160; c += 32) {
            asm volatile("cp.async.ca.shared.global [%0], [%1], 16;"
                         :: "r"(dst0 + (uint32_t)(c*16)), "l"(src0 + (size_t)c*16));
        }
        asm volatile("cp.async.commit_group;" ::: "memory");
        asm volatile("cp.async.wait_group 0;" ::: "memory");
        __syncwarp();
    }
    const float* xw = xsm + warp*XSLICE_FLOATS;

    int r = min(lid, 9);
    float wi[H_SZ], wf[H_SZ], wg[H_SZ], wo[H_SZ];
    #pragma unroll
    for (int j = 0; j < H_SZ; j++) {
        wi[j] = whh[(r     )*H_SZ + j];
        wf[j] = whh[(r + 10)*H_SZ + j];
        wg[j] = whh[(r + 20)*H_SZ + j];
        wo[j] = whh[(r + 30)*H_SZ + j];
    }

    float h[H_SZ];
    #pragma unroll
    for (int j = 0; j < H_SZ; j++) h[j] = 0.f;
    float c = 0.f;

    float ci = xw[r], cf = xw[10+r], cg = xw[20+r], co = xw[30+r];
    for (int t = 0; t < L_SZ; t++) {
        const float* nx = xw + (t+1)*G_SZ;     // t=215 overruns into pad
        float ni = nx[r], nf = nx[10+r], ng = nx[20+r], no = nx[30+r];

        float ia = ci, ib = 0.f, fa = cf, fb = 0.f;
        float ga = cg, gb = 0.f, oa = co, ob = 0.f;
        #pragma unroll
        for (int j = 0; j < 5; j++) {
            ia = fmaf(wi[j], h[j], ia);  ib = fmaf(wi[j+5], h[j+5], ib);
            fa = fmaf(wf[j], h[j], fa);  fb = fmaf(wf[j+5], h[j+5], fb);
            ga = fmaf(wg[j], h[j], ga);  gb = fmaf(wg[j+5], h[j+5], gb);
            oa = fmaf(wo[j], h[j], oa);  ob = fmaf(wo[j+5], h[j+5], ob);
        }
        float iv = fmaf(0.5f, tanh_a(0.5f*(ia+ib)), 0.5f);
        float fv = fmaf(0.5f, tanh_a(0.5f*(fa+fb)), 0.5f);
        float gv = tanh_a(ga+gb);
        float ov = fmaf(0.5f, tanh_a(0.5f*(oa+ob)), 0.5f);
        c = fmaf(fv, c, iv*gv);
        float hv = ov * tanh_a(c);
        #pragma unroll
        for (int j = 0; j < H_SZ; j++)
            h[j] = __shfl_sync(0xffffffffu, hv, j);
        ci = ni; cf = nf; cg = ng; co = no;
    }

    if (lid < 2) {
        float o = fcb[lid];
        #pragma unroll
        for (int j = 0; j < H_SZ; j++) o = fmaf(fcw[lid*H_SZ + j], h[j], o);
        out[b*2 + lid] = o;
    }
}

// ============================================================
extern "C" void kernel_launch(void* const* d_in, const int* in_sizes, int n_in,
                              void* d_out, int out_size)
{
    const float* x     = (const float*)d_in[0];
    const float* ctw   = (const float*)d_in[1];
    const float* ctb   = (const float*)d_in[2];
    const float* csw   = (const float*)d_in[3];
    const float* gamma = (const float*)d_in[4];
    const float* beta  = (const float*)d_in[5];
    const float* mean  = (const float*)d_in[6];
    const float* var   = (const float*)d_in[7];
    const float* wih   = (const float*)d_in[8];
    const float* whh   = (const float*)d_in[9];
    const float* bih   = (const float*)d_in[10];
    const float* bhh   = (const float*)d_in[11];
    const float* fcw   = (const float*)d_in[12];
    const float* fcb   = (const float*)d_in[13];
    float* out = (float*)d_out;

    cudaFuncSetAttribute(conv_kernel, cudaFuncAttributeMaxDynamicSharedMemorySize, CONV_SMEM_BYTES);
    cudaFuncSetAttribute(lstm_kernel, cudaFuncAttributeMaxDynamicSharedMemorySize, LSTM_SMEM_BYTES);

    prep_kernel<<<G_SZ, 256>>>(ctw, ctb, csw, gamma, beta, mean, var, wih, bih, bhh);
    conv_kernel<<<dim3(2, B_SZ), CT, CONV_SMEM_BYTES>>>(x);
    lstm_kernel<<<B_SZ/LSTM_WARPS, 32*LSTM_WARPS, LSTM_SMEM_BYTES>>>(whh, fcw, fcb, out);
}

// round 16
// speedup vs baseline: 1.5928x; 1.0396x over previous
#include <cuda_runtime.h>
#include <cuda_bf16.h>
#include <math.h>
#include <cstdint>

// Problem dims
#define B_SZ 512
#define T_IN 1125
#define E_SZ 5
#define C_SZ 40
#define L_SZ 216
#define G_SZ 40
#define H_SZ 10
#define KK   125

// ---- persistent scratch ----
__device__ __align__(16) float d_bg[G_SZ];
__device__ __align__(16) float d_xg[B_SZ*L_SZ*G_SZ];    // [b][t][g]
__device__ __align__(16) uint16_t d_Wbfhi[G_SZ*128];    // bf16 W[n][kk'], SWIZZLED stride 128
__device__ __align__(16) uint16_t d_Wbflo[G_SZ*128];    // kk' = e*25 + k reordering
__device__ int d_cnt = 0;                               // fold-completion counter

// swizzled byte offset for (row, col) in a stride-128-bf16 image
#define SWZ_OFF(row, col) ((uint32_t)((row)*256 + (((((col) >> 3)) ^ ((row) & 7)) << 4) + (((col) & 7) << 1)))

__device__ __forceinline__ float tanh_a(float x) {
    float r; asm("tanh.approx.f32 %0, %1;" : "=f"(r) : "f"(x)); return r;
}
__device__ __forceinline__ uint32_t smem_u32(const void* p) {
    uint32_t a;
    asm("{ .reg .u64 t; cvta.to.shared.u64 t, %1; cvt.u32.u64 %0, t; }" : "=r"(a) : "l"(p));
    return a;
}
__device__ __forceinline__ void ldsm_x4(uint32_t* r, uint32_t addr) {
    asm volatile("ldmatrix.sync.aligned.m8n8.x4.shared.b16 {%0,%1,%2,%3}, [%4];"
        : "=r"(r[0]), "=r"(r[1]), "=r"(r[2]), "=r"(r[3]) : "r"(addr));
}
__device__ __forceinline__ void ldsm_x2(uint32_t* r, uint32_t addr) {
    asm volatile("ldmatrix.sync.aligned.m8n8.x2.shared.b16 {%0,%1}, [%2];"
        : "=r"(r[0]), "=r"(r[1]) : "r"(addr));
}
__device__ __forceinline__ void mma_bf16(float* d, const uint32_t* a, const uint32_t* b) {
    asm volatile("mma.sync.aligned.m16n8k16.row.col.f32.bf16.bf16.f32 "
        "{%0,%1,%2,%3}, {%4,%5,%6,%7}, {%8,%9}, {%0,%1,%2,%3};"
        : "+f"(d[0]), "+f"(d[1]), "+f"(d[2]), "+f"(d[3])
        : "r"(a[0]), "r"(a[1]), "r"(a[2]), "r"(a[3]), "r"(b[0]), "r"(b[1]));
}
__device__ __forceinline__ uint16_t bf16_rn(float v) {
    __nv_bfloat16 h = __float2bfloat16(v);
    return *reinterpret_cast<uint16_t*>(&h);
}

// ============================================================
// FUSED Kernel 1: bid<40 = weight fold (R15 prep math verbatim,
// one gate per CTA, in dynamic smem); bid>=40 = conv tile.
// Conv phases A/B need no weights; poll happens only before
// phase C. 76,032 B smem -> 3 CTAs/SM.
// ============================================================
#define CT 256
#define PHALF 108
#define FOLD_CTAS 40
// conv smem byte offsets
#define OB_WHI  0          // 10240  (Bsum 11200B aliases [0, 11200) in phases A-B)
#define OB_WLO  10240      // -> 20480
#define OB_BG   20480      // 160 -> 20736 (pad)
#define OB_AHI  20736      // 108*256 = 27648 -> 48384
#define OB_ALO  48384      // 27648 -> 76032
#define CONV_SMEM_BYTES 76032

__global__ void __launch_bounds__(CT) conv_kernel(
        const float* __restrict__ x,
        const float* __restrict__ wt,     // [40][25]
        const float* __restrict__ tb,     // [40]
        const float* __restrict__ ws,     // [40][40][5]
        const float* __restrict__ gamma,
        const float* __restrict__ beta,
        const float* __restrict__ mean,
        const float* __restrict__ var,
        const float* __restrict__ wih,    // [40][40]
        const float* __restrict__ bih,
        const float* __restrict__ bhh)
{
    extern __shared__ char smc[];
    int tid  = threadIdx.x;

    if (blockIdx.x < FOLD_CTAS) {
        // ================= weight fold (R15 prep verbatim) =================
        float* sm      = (float*)smc;
        float* s_ws    = sm;            // 8000
        float* s_wt    = sm + 8000;     // 1000
        float* s_wr    = sm + 9000;
        float* s_wsc   = sm + 9040;
        float* s_shift = sm + 9080;
        float* s_tb    = sm + 9120;
        float* A_s     = sm + 9160;     // 200
        float* red     = sm + 9360;     // 8
        int t = tid;
        int g = blockIdx.x;

        for (int i = t; i < 2000; i += CT) ((float4*)s_ws)[i] = ((const float4*)ws)[i];
        for (int i = t; i < 250;  i += CT) ((float4*)s_wt)[i] = ((const float4*)wt)[i];
        if (t < C_SZ) {
            float sc = gamma[t] * rsqrtf(var[t] + 1e-5f);
            float wr = wih[g*C_SZ + t];
            s_wr[t]  = wr;
            s_wsc[t] = wr * sc;
            s_shift[t] = beta[t] - mean[t]*sc;
            s_tb[t] = tb[t];
        }
        __syncthreads();

        if (t < C_SZ*E_SZ) {
            int cp = t / E_SZ, e = t % E_SZ;
            float s = 0.f;
            #pragma unroll 8
            for (int c = 0; c < C_SZ; c++) s += s_wsc[c] * s_ws[c*200 + cp*E_SZ + e];
            A_s[t] = s;
        }
        __syncthreads();

        if (t < KK) {
            int k = t / E_SZ, e = t % E_SZ;
            float s = 0.f;
            #pragma unroll 8
            for (int cp = 0; cp < C_SZ; cp++) s += A_s[cp*E_SZ + e] * s_wt[cp*25 + k];
            float w = s * (1.0f/25.0f);
            int col = e*25 + k;                 // reordered kk'
            uint32_t bits = __float_as_uint(w);
            *(uint16_t*)((char*)d_Wbfhi + SWZ_OFF(g, col)) = (uint16_t)(bits >> 16);
            float lo = w - __uint_as_float(bits & 0xFFFF0000u);
            *(uint16_t*)((char*)d_Wbflo + SWZ_OFF(g, col)) = bf16_rn(lo);
        } else if (t < 128) {
            *(uint16_t*)((char*)d_Wbfhi + SWZ_OFF(g, t)) = 0;
            *(uint16_t*)((char*)d_Wbflo + SWZ_OFF(g, t)) = 0;
        }

        float part = 0.f;
        for (int idx = t; idx < 1600; idx += CT) {
            int c = idx / C_SZ, cp = idx % C_SZ;
            const float* w5 = &s_ws[c*200 + cp*E_SZ];
            float s5 = w5[0]+w5[1]+w5[2]+w5[3]+w5[4];
            part += s_wsc[c] * s_tb[cp] * s5;
        }
        if (t < C_SZ) part += s_wr[t] * s_shift[t];
        #pragma unroll
        for (int o = 16; o > 0; o >>= 1) part += __shfl_xor_sync(0xffffffffu, part, o);
        if ((t & 31) == 0) red[t >> 5] = part;
        __syncthreads();
        if (t == 0) {
            float s = red[0]+red[1]+red[2]+red[3]+red[4]+red[5]+red[6]+red[7];
            d_bg[g] = bih[g] + bhh[g] + s;
        }

        // release: make all this CTA's global writes visible, then count in
        __threadfence();
        __syncthreads();
        if (t == 0) atomicAdd(&d_cnt, 1);
        return;
    }

    // ================= conv tile (R15 verbatim + poll) =================
    int id   = blockIdx.x - FOLD_CTAS;
    int q    = id & 1;                 // 0/1 -> p [0,108) / [108,216)
    int b    = id >> 1;
    int lane = tid & 31;
    int w    = tid >> 5;
    uint32_t sbase = smem_u32(smc);

    // ---- Phase A: box sums -> Bsum[e][560] (fp32, in W region) ----
    float* Bsum = (float*)smc;
    {
        int e = tid % 5, seg = tid / 5;      // seg 0..50 (tid 255 idle)
        int t0 = seg*11;
        if (t0 < 560) {
            const float* xq = x + (size_t)b*(T_IN*E_SZ) + q*2700 + e;
            int t1 = min(t0+11, 560);
            float s = 0.f;
            #pragma unroll
            for (int j = 0; j < 25; j++) s += __ldg(xq + (t0+j)*5);
            Bsum[e*560 + t0] = s;
            for (int tt = t0+1; tt < t1; tt++) {
                s += __ldg(xq + (tt+24)*5) - __ldg(xq + (tt-1)*5);
                Bsum[e*560 + tt] = s;
            }
        }
    }
    __syncthreads();

    // ---- Phase B: vectorized pack -> swizzled Ahi/Alo ----
    for (int task = tid; task < PHALF*16; task += CT) {
        int pl = task >> 4;
        int c  = task & 15;
        float v[8];
        #pragma unroll
        for (int j = 0; j < 8; j++) {
            int kk = 8*c + j;
            int e  = kk / 25;
            int k  = kk - 25*e;
            v[j] = (kk < KK) ? Bsum[e*560 + 5*pl + k] : 0.f;
        }
        uint32_t hi[4], lo[4];
        #pragma unroll
        for (int j = 0; j < 4; j++) {
            uint32_t b0 = __float_as_uint(v[2*j]);
            uint32_t b1 = __float_as_uint(v[2*j+1]);
            hi[j] = __byte_perm(b0, b1, 0x7632);
            float l0 = v[2*j]   - __uint_as_float(b0 & 0xFFFF0000u);
            float l1 = v[2*j+1] - __uint_as_float(b1 & 0xFFFF0000u);
            asm("cvt.rn.bf16x2.f32 %0, %1, %2;" : "=r"(lo[j]) : "f"(l1), "f"(l0));
        }
        uint32_t off = (uint32_t)(pl*256 + (((c) ^ (pl & 7)) << 4));
        *(uint4*)(smc + OB_AHI + off) = make_uint4(hi[0], hi[1], hi[2], hi[3]);
        *(uint4*)(smc + OB_ALO + off) = make_uint4(lo[0], lo[1], lo[2], lo[3]);
    }

    // ---- poll for fold completion (one thread), then stage W ----
    if (tid == 0) {
        int v;
        do {
            asm volatile("ld.acquire.gpu.s32 %0, [%1];" : "=r"(v) : "l"(&d_cnt) : "memory");
            if (v < FOLD_CTAS) __nanosleep(100);
        } while (v < FOLD_CTAS);
    }
    __syncthreads();

    // ---- Phase C: stage W (overwrite Bsum region) + bias ----
    {
        const uint4* ghi = (const uint4*)d_Wbfhi;
        const uint4* glo = (const uint4*)d_Wbflo;
        uint4* shi = (uint4*)(smc + OB_WHI);
        uint4* slo = (uint4*)(smc + OB_WLO);
        for (int i = tid; i < 640; i += CT) { shi[i] = ghi[i]; slo[i] = glo[i]; }
    }
    if (tid < G_SZ) ((float*)(smc + OB_BG))[tid] = d_bg[tid];
    __syncthreads();

    // ---- Phase D: MMA (R15 verbatim) ----
    if (w < 7) {
        int ar = 16*w + (lane & 15);
        int ar2 = min(ar, PHALF-1);
        uint32_t a8 = (uint32_t)(lane >> 4);
        uint32_t arow_base = (uint32_t)(ar2*256);
        uint32_t apl7 = (uint32_t)(ar2 & 7);
        int bl = lane & 15;
        uint32_t brow = (uint32_t)(bl & 7);
        uint32_t bsel = (uint32_t)((bl >> 3) & 1);

        float D[5][4];
        #pragma unroll
        for (int nt = 0; nt < 5; nt++)
            #pragma unroll
            for (int j = 0; j < 4; j++) D[nt][j] = 0.f;

        #pragma unroll
        for (int ks = 0; ks < 8; ks++) {
            uint32_t achunk = ((uint32_t)(2*ks) + a8) ^ apl7;
            uint32_t aoff = arow_base + (achunk << 4);
            uint32_t ahi[4], alo[4];
            ldsm_x4(ahi, sbase + OB_AHI + aoff);
            ldsm_x4(alo, sbase + OB_ALO + aoff);
            uint32_t bchunk = ((uint32_t)(2*ks) + bsel) ^ brow;
            #pragma unroll
            for (int nt = 0; nt < 5; nt++) {
                uint32_t boff = ((uint32_t)(nt*8) + brow)*256u + (bchunk << 4);
                uint32_t bhi[2], blo[2];
                ldsm_x2(bhi, sbase + OB_WHI + boff);
                ldsm_x2(blo, sbase + OB_WLO + boff);
                mma_bf16(D[nt], ahi, bhi);
                mma_bf16(D[nt], ahi, blo);
                mma_bf16(D[nt], alo, bhi);
            }
        }

        // epilogue: add bias, store [b][t][g]
        const float* bgs = (const float*)(smc + OB_BG);
        int r0 = lane >> 2;
        int cp = (lane & 3) * 2;
        float* dst = d_xg + (size_t)b*(L_SZ*G_SZ) + (size_t)(q*PHALF)*G_SZ;
        int p_a = 16*w + r0;
        int p_b = p_a + 8;
        #pragma unroll
        for (int nt = 0; nt < 5; nt++) {
            int g = nt*8 + cp;
            float b0v = bgs[g], b1v = bgs[g+1];
            if (p_a < PHALF) {
                float2 v = make_float2(D[nt][0] + b0v, D[nt][1] + b1v);
                *(float2*)(dst + p_a*G_SZ + g) = v;
            }
            if (p_b < PHALF) {
                float2 v = make_float2(D[nt][2] + b0v, D[nt][3] + b1v);
                *(float2*)(dst + p_b*G_SZ + g) = v;
            }
        }
    }
}

// ============================================================
// Kernel 2: LSTM scan + FC (R15 verbatim) + counter reset.
// ============================================================
#define LSTM_WARPS 4
#define XSLICE_FLOATS (L_SZ*G_SZ)            // 8640
#define XSLICE_BYTES  (XSLICE_FLOATS*4)      // 34560
#define LSTM_SMEM_BYTES (LSTM_WARPS*XSLICE_BYTES + 256)

__global__ void __launch_bounds__(32*LSTM_WARPS) lstm_kernel(
        const float* __restrict__ whh,  // [40][10]
        const float* __restrict__ fcw,  // [2][10]
        const float* __restrict__ fcb,
        float* __restrict__ out)
{
    extern __shared__ float xsm[];
    int warp = threadIdx.x >> 5;
    int lid  = threadIdx.x & 31;
    int b    = blockIdx.x*LSTM_WARPS + warp;

    if (blockIdx.x == 0 && threadIdx.x == 0) d_cnt = 0;   // reset for next replay

    {
        uint32_t dst0 = smem_u32(xsm) + warp*XSLICE_BYTES;
        const char* src0 = (const char*)(d_xg + (size_t)b*XSLICE_FLOATS);
        for (int c = lid; c < 2160; c += 32) {
            asm volatile("cp.async.ca.shared.global [%0], [%1], 16;"
                         :: "r"(dst0 + (uint32_t)(c*16)), "l"(src0 + (size_t)c*16));
        }
        asm volatile("cp.async.commit_group;" ::: "memory");
        asm volatile("cp.async.wait_group 0;" ::: "memory");
        __syncwarp();
    }
    const float* xw = xsm + warp*XSLICE_FLOATS;

    int r = min(lid, 9);
    float wi[H_SZ], wf[H_SZ], wg[H_SZ], wo[H_SZ];
    #pragma unroll
    for (int j = 0; j < H_SZ; j++) {
        wi[j] = whh[(r     )*H_SZ + j];
        wf[j] = whh[(r + 10)*H_SZ + j];
        wg[j] = whh[(r + 20)*H_SZ + j];
        wo[j] = whh[(r + 30)*H_SZ + j];
    }

    float h[H_SZ];
    #pragma unroll
    for (int j = 0; j < H_SZ; j++) h[j] = 0.f;
    float c = 0.f;

    float ci = xw[r], cf = xw[10+r], cg = xw[20+r], co = xw[30+r];
    for (int t = 0; t < L_SZ; t++) {
        const float* nx = xw + (t+1)*G_SZ;     // t=215 overruns into pad
        float ni = nx[r], nf = nx[10+r], ng = nx[20+r], no = nx[30+r];

        float ia = ci, ib = 0.f, fa = cf, fb = 0.f;
        float ga = cg, gb = 0.f, oa = co, ob = 0.f;
        #pragma unroll
        for (int j = 0; j < 5; j++) {
            ia = fmaf(wi[j], h[j], ia);  ib = fmaf(wi[j+5], h[j+5], ib);
            fa = fmaf(wf[j], h[j], fa);  fb = fmaf(wf[j+5], h[j+5], fb);
            ga = fmaf(wg[j], h[j], ga);  gb = fmaf(wg[j+5], h[j+5], gb);
            oa = fmaf(wo[j], h[j], oa);  ob = fmaf(wo[j+5], h[j+5], ob);
        }
        float iv = fmaf(0.5f, tanh_a(0.5f*(ia+ib)), 0.5f);
        float fv = fmaf(0.5f, tanh_a(0.5f*(fa+fb)), 0.5f);
        float gv = tanh_a(ga+gb);
        float ov = fmaf(0.5f, tanh_a(0.5f*(oa+ob)), 0.5f);
        c = fmaf(fv, c, iv*gv);
        float hv = ov * tanh_a(c);
        #pragma unroll
        for (int j = 0; j < H_SZ; j++)
            h[j] = __shfl_sync(0xffffffffu, hv, j);
        ci = ni; cf = nf; cg = ng; co = no;
    }

    if (lid < 2) {
        float o = fcb[lid];
        #pragma unroll
        for (int j = 0; j < H_SZ; j++) o = fmaf(fcw[lid*H_SZ + j], h[j], o);
        out[b*2 + lid] = o;
    }
}

// ============================================================
extern "C" void kernel_launch(void* const* d_in, const int* in_sizes, int n_in,
                              void* d_out, int out_size)
{
    const float* x     = (const float*)d_in[0];
    const float* ctw   = (const float*)d_in[1];
    const float* ctb   = (const float*)d_in[2];
    const float* csw   = (const float*)d_in[3];
    const float* gamma = (const float*)d_in[4];
    const float* beta  = (const float*)d_in[5];
    const float* mean  = (const float*)d_in[6];
    const float* var   = (const float*)d_in[7];
    const float* wih   = (const float*)d_in[8];
    const float* whh   = (const float*)d_in[9];
    const float* bih   = (const float*)d_in[10];
    const float* bhh   = (const float*)d_in[11];
    const float* fcw   = (const float*)d_in[12];
    const float* fcb   = (const float*)d_in[13];
    float* out = (float*)d_out;

    cudaFuncSetAttribute(conv_kernel, cudaFuncAttributeMaxDynamicSharedMemorySize, CONV_SMEM_BYTES);
    cudaFuncSetAttribute(lstm_kernel, cudaFuncAttributeMaxDynamicSharedMemorySize, LSTM_SMEM_BYTES);

    conv_kernel<<<FOLD_CTAS + 2*B_SZ, CT, CONV_SMEM_BYTES>>>(
        x, ctw, ctb, csw, gamma, beta, mean, var, wih, bih, bhh);
    lstm_kernel<<<B_SZ/LSTM_WARPS, 32*LSTM_WARPS, LSTM_SMEM_BYTES>>>(whh, fcw, fcb, out);
}